// round 3
// baseline (speedup 1.0000x reference)
#include <cuda_runtime.h>

// Problem constants
#define SS        196              // S*S = 14*14
#define DCH       30               // 5*B + C
#define NBATCH    4096
#define QPB       49               // quads per batch image (196/4)
#define NQUADS    (NBATCH * QPB)   // 200704
#define BLOCK     256
#define GRID      (NQUADS / BLOCK) // 784 exactly
#define LAMBDA_COORD 5.0f
#define LAMBDA_NOOBJ 0.5f

__device__ float g_partials[GRID];
__device__ unsigned int g_ticket = 0;

__global__ void __launch_bounds__(BLOCK) yolo_fused4_kernel(
    const float* __restrict__ pred,
    const float* __restrict__ tgt,
    float* __restrict__ out)
{
    const int q  = blockIdx.x * BLOCK + threadIdx.x;   // quad index, < NQUADS (exact grid)
    const int n  = q / QPB;
    const int qs = q - n * QPB;
    const size_t base = (size_t)n * DCH * SS + qs * 4; // 16B-aligned
    const float* __restrict__ pb = pred + base;
    const float* __restrict__ tb = tgt  + base;

    // ---- box channels d=0..9, 4 cells wide ----
    float p[40], t[40];
#pragma unroll
    for (int d = 0; d < 10; ++d) {
        const float4 v = *(const float4*)(pb + d * SS);
        const float4 w = *(const float4*)(tb + d * SS);
        p[4*d+0] = v.x; p[4*d+1] = v.y; p[4*d+2] = v.z; p[4*d+3] = v.w;
        t[4*d+0] = w.x; t[4*d+1] = w.y; t[4*d+2] = w.z; t[4*d+3] = w.w;
    }

    // ---- class loss d=10..29, accumulated on the fly ----
    float cls[4] = {0.f, 0.f, 0.f, 0.f};
#pragma unroll
    for (int d = 10; d < DCH; ++d) {
        const float4 v = *(const float4*)(pb + d * SS);
        const float4 w = *(const float4*)(tb + d * SS);
        float dx = v.x - w.x; cls[0] += dx * dx;
        float dy = v.y - w.y; cls[1] += dy * dy;
        float dz = v.z - w.z; cls[2] += dz * dz;
        float dw = v.w - w.w; cls[3] += dw * dw;
    }

    // ---- per-cell loss, 4 cells ----
    const float invS = 1.0f / 14.0f;
    float loss = 0.0f;
#pragma unroll
    for (int c = 0; c < 4; ++c) {
        const float pp0 = p[c],      pp1 = p[4+c],  pp2 = p[8+c],  pp3 = p[12+c], pp4 = p[16+c];
        const float pp5 = p[20+c],   pp6 = p[24+c], pp7 = p[28+c], pp8 = p[32+c], pp9 = p[36+c];
        const float tp0 = t[c],      tp1 = t[4+c],  tp2 = t[8+c],  tp3 = t[12+c], tp4 = t[16+c];
        const float tp5 = t[20+c],   tp6 = t[24+c], tp7 = t[28+c], tp8 = t[32+c], tp9 = t[36+c];

        const float obj   = (tp4 > 0.0f)  ? 1.0f : 0.0f;
        const float noobj = (tp4 == 0.0f) ? 1.0f : 0.0f;

        // no-object confidence loss (conf channels d=4 and d=9)
        const float d0 = pp4 - tp4;
        const float d1 = pp9 - tp9;
        const float l_noobj = noobj * (d0 * d0 + d1 * d1);

        // target box (box 0 of target)
        const float t_cx = tp0 * invS, t_cy = tp1 * invS;
        const float t_ltx = t_cx - 0.5f * tp2;
        const float t_lty = t_cy - 0.5f * tp3;
        const float t_rbx = t_cx + 0.5f * tp2;
        const float t_rby = t_cy + 0.5f * tp3;
        const float t_area = (t_rbx - t_ltx) * (t_rby - t_lty);

        // IoU box 0
        float iou0, iou1;
        {
            const float p_cx = pp0 * invS, p_cy = pp1 * invS;
            const float p_ltx = p_cx - 0.5f * pp2;
            const float p_lty = p_cy - 0.5f * pp3;
            const float p_rbx = p_cx + 0.5f * pp2;
            const float p_rby = p_cy + 0.5f * pp3;
            const float wx = fmaxf(fminf(t_rbx, p_rbx) - fmaxf(t_ltx, p_ltx), 0.0f);
            const float wy = fmaxf(fminf(t_rby, p_rby) - fmaxf(t_lty, p_lty), 0.0f);
            const float inter  = wx * wy;
            const float p_area = (p_rbx - p_ltx) * (p_rby - p_lty);
            float un = t_area + p_area - inter;
            if (un == 0.0f) un = 1.0f;
            iou0 = inter / un;
        }
        // IoU box 1
        {
            const float p_cx = pp5 * invS, p_cy = pp6 * invS;
            const float p_ltx = p_cx - 0.5f * pp7;
            const float p_lty = p_cy - 0.5f * pp8;
            const float p_rbx = p_cx + 0.5f * pp7;
            const float p_rby = p_cy + 0.5f * pp8;
            const float wx = fmaxf(fminf(t_rbx, p_rbx) - fmaxf(t_ltx, p_ltx), 0.0f);
            const float wy = fmaxf(fminf(t_rby, p_rby) - fmaxf(t_lty, p_lty), 0.0f);
            const float inter  = wx * wy;
            const float p_area = (p_rbx - p_ltx) * (p_rby - p_lty);
            float un = t_area + p_area - inter;
            if (un == 0.0f) un = 1.0f;
            iou1 = inter / un;
        }

        // argmax (strict > so box 0 wins ties)
        const bool  r1      = (iou1 > iou0);
        const float max_iou = fmaxf(iou0, iou1);

        const float bpr0 = r1 ? pp5 : pp0;
        const float bpr1 = r1 ? pp6 : pp1;
        const float bpr2 = r1 ? pp7 : pp2;
        const float bpr3 = r1 ? pp8 : pp3;
        const float bpr4 = r1 ? pp9 : pp4;
        const float btr0 = r1 ? tp5 : tp0;
        const float btr1 = r1 ? tp6 : tp1;
        const float btr2 = r1 ? tp7 : tp2;
        const float btr3 = r1 ? tp8 : tp3;

        const float e0 = bpr0 - btr0, e1 = bpr1 - btr1;
        const float e2 = bpr2 - btr2, e3 = bpr3 - btr3;
        const float l_coord = e0 * e0 + e1 * e1 + e2 * e2 + e3 * e3;
        const float ec = bpr4 - max_iou;

        loss += obj * (LAMBDA_COORD * l_coord + ec * ec + cls[c])
              + LAMBDA_NOOBJ * l_noobj;
    }

    // ---- block reduction (deterministic) ----
    __shared__ float warp_sums[BLOCK / 32];
    __shared__ bool  is_last;
#pragma unroll
    for (int off = 16; off > 0; off >>= 1)
        loss += __shfl_xor_sync(0xFFFFFFFFu, loss, off);
    const int lane = threadIdx.x & 31;
    const int wid  = threadIdx.x >> 5;
    if (lane == 0) warp_sums[wid] = loss;
    __syncthreads();
    if (wid == 0) {
        float v = (lane < BLOCK / 32) ? warp_sums[lane] : 0.0f;
#pragma unroll
        for (int off = 4; off > 0; off >>= 1)
            v += __shfl_xor_sync(0xFFFFFFFFu, v, off);
        if (lane == 0) {
            g_partials[blockIdx.x] = v;
            __threadfence();
            unsigned int tk = atomicAdd(&g_ticket, 1u);
            is_last = (tk == GRID - 1);
        }
    }
    __syncthreads();

    // ---- last block: final reduce over all partials (L2-hot) ----
    if (is_last) {
        float s2 = 0.0f;
        for (int i = threadIdx.x; i < GRID; i += BLOCK)
            s2 += g_partials[i];
#pragma unroll
        for (int off = 16; off > 0; off >>= 1)
            s2 += __shfl_xor_sync(0xFFFFFFFFu, s2, off);
        if (lane == 0) warp_sums[wid] = s2;
        __syncthreads();
        if (wid == 0) {
            float v = (lane < BLOCK / 32) ? warp_sums[lane] : 0.0f;
#pragma unroll
            for (int off = 4; off > 0; off >>= 1)
                v += __shfl_xor_sync(0xFFFFFFFFu, v, off);
            if (lane == 0) {
                out[0] = v / (float)NBATCH;
                __threadfence();
                g_ticket = 0;   // reset for next graph replay
            }
        }
    }
}

extern "C" void kernel_launch(void* const* d_in, const int* in_sizes, int n_in,
                              void* d_out, int out_size)
{
    const float* pred = (const float*)d_in[0];
    const float* tgt  = (const float*)d_in[1];
    float* out = (float*)d_out;
    yolo_fused4_kernel<<<GRID, BLOCK>>>(pred, tgt, out);
}